// round 7
// baseline (speedup 1.0000x reference)
#include <cuda_runtime.h>
#include <cstdint>

// Problem constants
#define NB   2
#define NS   2048
#define ND   512
#define NH   8
#define NQ   64
#define NHD  64
#define NBS  (NB*NS)             // 4096 tokens
#define QKV_ELEMS (NB*NH*NS*NHD) // 2,097,152

// Scratch (device globals; no allocations allowed)
__device__ float g_geT[3][2][NQ*NQ];     // (gr@ent)^T per projection, tf32
__device__ float g_m2T[NH][NQ*NHD];      // ((q_meas.h w_h)@interf_h/8)^T, tf32
__device__ float g_encT[3][NQ*ND];       // enc^T [64][512], tf32
__device__ float g_measT[3][ND*NQ];      // meas^T [512][64], w folded (p=1,2), tf32
__device__ float g_woT[ND*ND];           // w_out^T [512][512], tf32
__device__ float g_qkv[3][QKV_ELEMS];    // qm / ks / vs in (b,h,s,d), tf32-rounded
__device__ float g_ao[NBS*ND];           // attention out, (b,s,D)

// ---------------------------------------------------------------------------
// helpers
// ---------------------------------------------------------------------------
__device__ __forceinline__ uint32_t fbits(float x) { return __float_as_uint(x); }

__device__ __forceinline__ float to_tf32(float x) {
    float r;
    asm("cvt.rna.tf32.f32 %0, %1;" : "=f"(r) : "f"(x));
    return r;
}

__device__ __forceinline__ void mma_tf32(float d[4], const uint32_t a[4],
                                         const uint32_t b[2], const float c[4]) {
    asm volatile("mma.sync.aligned.m16n8k8.row.col.f32.tf32.tf32.f32 "
                 "{%0,%1,%2,%3}, {%4,%5,%6,%7}, {%8,%9}, {%10,%11,%12,%13};"
                 : "=f"(d[0]), "=f"(d[1]), "=f"(d[2]), "=f"(d[3])
                 : "r"(a[0]), "r"(a[1]), "r"(a[2]), "r"(a[3]),
                   "r"(b[0]), "r"(b[1]),
                   "f"(c[0]), "f"(c[1]), "f"(c[2]), "f"(c[3]));
}

#define LDK 68
#define LDV 72

#define CP_ASYNC16(dst, src) \
    asm volatile("cp.async.cg.shared.global [%0], [%1], 16;" :: "r"(dst), "l"(src))
#define CP_COMMIT()  asm volatile("cp.async.commit_group;")
#define CP_WAIT0()   asm volatile("cp.async.wait_group 0;")

// nrows x 64 tile load, global contiguous, smem stride lds (plain ld/st)
template<int NROWS>
__device__ __forceinline__ void load_rows(float* s, int lds, const float* g, int tid) {
#pragma unroll
    for (int i = 0; i < NROWS/16; i++) {
        int idx = tid + 256 * i;
        float4 v = reinterpret_cast<const float4*>(g)[idx];
        int row = idx >> 4;
        int c   = (idx & 15) * 4;
        s[row*lds + c + 0] = v.x;
        s[row*lds + c + 1] = v.y;
        s[row*lds + c + 2] = v.z;
        s[row*lds + c + 3] = v.w;
    }
}

// async NROWSx64 tile fill; global row stride ldg (floats); smem row stride lds
template<int NROWS>
__device__ __forceinline__ void cpa_rows(uint32_t s_u32, int lds, const float* g, int ldg, int tid) {
#pragma unroll
    for (int i = 0; i < NROWS/16; i++) {
        int idx = tid + 256 * i;
        int row = idx >> 4;
        int c   = (idx & 15) * 4;
        CP_ASYNC16(s_u32 + (uint32_t)(row*lds + c)*4u, g + (size_t)row*ldg + c);
    }
}

// ---------------------------------------------------------------------------
// Kernel 1: prep — folded gates (transposed), M2^T, enc^T, meas^T(.w), w_out^T
// ---------------------------------------------------------------------------
__device__ __forceinline__ void transpose_tile(float* dst, int ldd, const float* src, int ldsrc,
                                               const float* rowscale, int tid, float* sg) {
    for (int idx = tid; idx < 4096; idx += 256) {
        int r = idx >> 6, c = idx & 63;
        sg[r*65 + c] = src[(size_t)r*ldsrc + c];
    }
    __syncthreads();
    for (int idx = tid; idx < 4096; idx += 256) {
        int n = idx >> 6, k = idx & 63;
        float v = sg[k*65 + n];
        if (rowscale) v *= rowscale[n];
        dst[(size_t)n*ldd + k] = to_tf32(v);
    }
    __syncthreads();
}

__global__ void k_prep(const float* __restrict__ grq, const float* __restrict__ giq, const float* __restrict__ entq,
                       const float* __restrict__ grk, const float* __restrict__ gik, const float* __restrict__ entk,
                       const float* __restrict__ grv, const float* __restrict__ giv, const float* __restrict__ entv,
                       const float* __restrict__ qmeas, const float* __restrict__ kmeas, const float* __restrict__ vmeas,
                       const float* __restrict__ qenc, const float* __restrict__ kenc, const float* __restrict__ venc,
                       const float* __restrict__ supw, const float* __restrict__ interf,
                       const float* __restrict__ wout) {
    __shared__ float sg[64*65];
    __shared__ float se[64*64];
    const int bx = blockIdx.x;
    const int tid = threadIdx.x;

    if (bx < 6) {
        int p = bx >> 1, which = bx & 1;
        const float* g = (p == 0) ? (which ? giq : grq)
                       : (p == 1) ? (which ? gik : grk)
                                  : (which ? giv : grv);
        const float* e = (p == 0) ? entq : (p == 1) ? entk : entv;
        for (int i = tid; i < 4096; i += 256) { sg[(i>>6)*65 + (i&63)] = g[i]; se[i] = e[i]; }
        __syncthreads();
        for (int idx = tid; idx < 4096; idx += 256) {
            int r = idx >> 6, c = idx & 63;
            float acc = 0.f;
#pragma unroll 8
            for (int k = 0; k < 64; k++) acc = fmaf(sg[r*65 + k], se[k*64 + c], acc);
            g_geT[p][which][c*64 + r] = to_tf32(acc);
        }
    } else if (bx < 14) {
        int h = bx - 6;
        for (int i = tid; i < 4096; i += 256) {
            int r = i >> 6, c = i & 63;
            sg[r*65 + c] = qmeas[(size_t)r * ND + h*64 + c] * supw[h*64 + c];
            se[i] = interf[(size_t)h*4096 + i];
        }
        __syncthreads();
        for (int idx = tid; idx < 4096; idx += 256) {
            int r = idx >> 6, c = idx & 63;
            float acc = 0.f;
#pragma unroll 8
            for (int k = 0; k < 64; k++) acc = fmaf(sg[r*65 + k], se[k*64 + c], acc);
            g_m2T[h][c*64 + r] = to_tf32(acc * 0.125f);
        }
    } else if (bx < 17) {
        int p = bx - 14;
        const float* enc = (p == 0) ? qenc : (p == 1) ? kenc : venc;
        for (int kt = 0; kt < 8; kt++)
            transpose_tile(g_encT[p] + kt*64, 512, enc + (size_t)kt*64*64, 64, nullptr, tid, sg);
    } else if (bx < 19) {
        int p = bx - 16;   // 1 or 2
        const float* meas = (p == 1) ? kmeas : vmeas;
        for (int ct = 0; ct < 8; ct++)
            transpose_tile(g_measT[p] + (size_t)ct*4096, 64, meas + ct*64, 512, supw + ct*64, tid, sg);
    } else {
        int t = bx - 19;   // 0..63
        int i = t >> 3, j = t & 7;
        transpose_tile(g_woT + (size_t)(j*64)*512 + i*64, 512,
                       wout + (size_t)(i*64)*512 + j*64, 512, nullptr, tid, sg);
    }
}

// ---------------------------------------------------------------------------
// C-frag (16x64, sf[8][4]) -> A-frags (a[kk][4]) via quad shuffles, tf32-rounded.
// Same pattern as k_attn's P@V conversion.
// ---------------------------------------------------------------------------
__device__ __forceinline__ void cfrag_to_afrag(uint32_t (&a)[8][4], const float (&sf)[8][4],
                                               int lane) {
    const int srcA = (lane & ~3) + ((lane & 3) >> 1);
    const int srcB = srcA + 2;
    const bool odd = (lane & 1);
#pragma unroll
    for (int kk = 0; kk < 8; kk++) {
        float p0 = __shfl_sync(0xffffffffu, sf[kk][0], srcA);
        float p1 = __shfl_sync(0xffffffffu, sf[kk][1], srcA);
        float p2 = __shfl_sync(0xffffffffu, sf[kk][2], srcA);
        float p3 = __shfl_sync(0xffffffffu, sf[kk][3], srcA);
        float r0 = __shfl_sync(0xffffffffu, sf[kk][0], srcB);
        float r1 = __shfl_sync(0xffffffffu, sf[kk][1], srcB);
        float r2 = __shfl_sync(0xffffffffu, sf[kk][2], srcB);
        float r3 = __shfl_sync(0xffffffffu, sf[kk][3], srcB);
        a[kk][0] = fbits(to_tf32(odd ? p1 : p0));
        a[kk][1] = fbits(to_tf32(odd ? p3 : p2));
        a[kk][2] = fbits(to_tf32(odd ? r1 : r0));
        a[kk][3] = fbits(to_tf32(odd ? r3 : r2));
    }
}

// 16x64 per-warp gemm: C += A(regs) * B(smem tile, stride LDK)
__device__ __forceinline__ void gemm_regA(float (&sf)[8][4], const uint32_t (&a)[8][4],
                                          const float* sB, int g4, int l4) {
#pragma unroll
    for (int kk = 0; kk < 8; kk++) {
#pragma unroll
        for (int ns = 0; ns < 8; ns++) {
            const float* bp = sB + (ns*8 + g4)*LDK + kk*8 + l4;
            uint32_t b[2] = { fbits(bp[0]), fbits(bp[4]) };
            mma_tf32(sf[ns], a[kk], b, sf[ns]);
        }
    }
}

#define ZERO84(f) {                                      \
    _Pragma("unroll") for (int _n = 0; _n < 8; _n++)     \
    _Pragma("unroll") for (int _j = 0; _j < 4; _j++) (f)[_n][_j] = 0.f; }

// ---------------------------------------------------------------------------
// Kernel 2: fused QNL, FA2-style. 128 rows/block, warp owns 16x64.
//  XE and prob live in C-frags; cp.async double-buffered tiles.
// ---------------------------------------------------------------------------
#define QNL_SMEM_FLOATS (2*128*LDK + 2*64*LDK)   // 104448 B

__global__ void __launch_bounds__(256) k_qnl(const float* __restrict__ x) {
    extern __shared__ float sm[];
    float* sX0 = sm;
    float* sX1 = sm + 128*LDK;
    float* sB0 = sm + 2*128*LDK;
    float* sB1 = sB0 + 64*LDK;

    const int p  = blockIdx.x >> 5;          // 0..2
    const int rt = blockIdx.x & 31;          // 0..31
    const int tid  = threadIdx.x;
    const int lane = tid & 31;
    const int warp = tid >> 5;
    const int g4 = lane >> 2;
    const int l4 = lane & 3;
    const int r0 = rt * 128;

    const uint32_t sX0u = (uint32_t)__cvta_generic_to_shared(sX0);
    const uint32_t sX1u = (uint32_t)__cvta_generic_to_shared(sX1);
    const uint32_t sB0u = (uint32_t)__cvta_generic_to_shared(sB0);
    const uint32_t sB1u = (uint32_t)__cvta_generic_to_shared(sB1);

    // ---- phase 1: XE = X(128x512) @ enc  -> xeC[8][4] ----
    cpa_rows<128>(sX0u, LDK, x + (size_t)r0*ND, ND, tid);
    cpa_rows<64> (sB0u, LDK, g_encT[p], 512, tid);
    CP_COMMIT();

    float xeC[8][4];
    ZERO84(xeC);
    for (int kt = 0; kt < 8; kt++) {
        CP_WAIT0();
        __syncthreads();
        if (kt + 1 < 8) {
            cpa_rows<128>((kt & 1) ? sX0u : sX1u, LDK, x + (size_t)r0*ND + (kt+1)*64, ND, tid);
            cpa_rows<64> ((kt & 1) ? sB0u : sB1u, LDK, g_encT[p] + (kt+1)*64, 512, tid);
            CP_COMMIT();
        }
        const float* sX = (kt & 1) ? sX1 : sX0;
        const float* sB = (kt & 1) ? sB1 : sB0;
        const float* abase = sX + (warp*16 + g4)*LDK + l4;
#pragma unroll
        for (int kk = 0; kk < 8; kk++) {
            const float* ap = abase + kk*8;
            uint32_t a[4];
            a[0] = fbits(to_tf32(ap[0]));
            a[1] = fbits(to_tf32(ap[8*LDK]));
            a[2] = fbits(to_tf32(ap[4]));
            a[3] = fbits(to_tf32(ap[8*LDK + 4]));
#pragma unroll
            for (int ns = 0; ns < 8; ns++) {
                const float* bp = sB + (ns*8 + g4)*LDK + kk*8 + l4;
                uint32_t b[2] = { fbits(bp[0]), fbits(bp[4]) };
                mma_tf32(xeC[ns], a, b, xeC[ns]);
            }
        }
    }

    // ---- phase 2: er/ei = XE @ geT[0/1]; prob = er^2+ei^2 ----
    __syncthreads();                       // all warps done with sB0/sB1
    cpa_rows<64>(sB0u, LDK, g_geT[p][0], 64, tid);
    cpa_rows<64>(sB1u, LDK, g_geT[p][1], 64, tid);
    CP_COMMIT();

    uint32_t xeA[8][4];
    cfrag_to_afrag(xeA, xeC, lane);        // overlap shuffles with loads

    CP_WAIT0();
    __syncthreads();
    float erC[8][4];
    ZERO84(erC);
    gemm_regA(erC, xeA, sB0, g4, l4);
    float eiC[8][4];
    ZERO84(eiC);
    gemm_regA(eiC, xeA, sB1, g4, l4);
#pragma unroll
    for (int ns = 0; ns < 8; ns++)
#pragma unroll
        for (int j = 0; j < 4; j++)
            erC[ns][j] = erC[ns][j]*erC[ns][j] + eiC[ns][j]*eiC[ns][j];

    uint32_t probA[8][4];
    cfrag_to_afrag(probA, erC, lane);

    // ---- phase 3: out[ct] = prob @ (m2T[ct] or measT[p][ct]) ----
    __syncthreads();                       // all warps done reading sB0/sB1
    {
        const float* b0 = (p == 0) ? g_m2T[0] : g_measT[p];
        cpa_rows<64>(sB0u, LDK, b0, 64, tid);
        CP_COMMIT();
    }
    const int b  = r0 >> 11;
    const int s0 = r0 & 2047;
    for (int ct = 0; ct < 8; ct++) {
        CP_WAIT0();
        __syncthreads();
        if (ct + 1 < 8) {
            const float* bn = (p == 0) ? g_m2T[ct+1] : (g_measT[p] + (size_t)(ct+1)*4096);
            cpa_rows<64>((ct & 1) ? sB0u : sB1u, LDK, bn, 64, tid);
            CP_COMMIT();
        }
        const float* sB = (ct & 1) ? sB1 : sB0;
        float oC[8][4];
        ZERO84(oC);
        gemm_regA(oC, probA, sB, g4, l4);

        float* outp = g_qkv[p] + ((size_t)(b*NH + ct)*NS + s0) * NHD;
        const int r = warp*16 + g4;
#pragma unroll
        for (int ns = 0; ns < 8; ns++) {
            int c = ns*8 + 2*l4;
            outp[(size_t)r*64 + c]       = to_tf32(oC[ns][0]);
            outp[(size_t)r*64 + c + 1]   = to_tf32(oC[ns][1]);
            outp[(size_t)(r+8)*64 + c]   = to_tf32(oC[ns][2]);
            outp[(size_t)(r+8)*64 + c+1] = to_tf32(oC[ns][3]);
        }
    }
}

// ---------------------------------------------------------------------------
// Kernel 3: flash attention, FA2-style register-resident (unchanged)
// ---------------------------------------------------------------------------
#define ATT_SMEM_FLOATS (2*64*LDK + 2*64*LDV)

__global__ void __launch_bounds__(256) k_attn() {
    extern __shared__ float sm[];
    float* sK0 = sm;
    float* sK1 = sm + 64*LDK;
    float* sV0 = sm + 2*64*LDK;
    float* sV1 = sV0 + 64*LDV;

    const int tid  = threadIdx.x;
    const int lane = tid & 31;
    const int warp = tid >> 5;
    const int bh = blockIdx.x >> 4;
    const int qt = blockIdx.x & 15;
    const int g4 = lane >> 2;
    const int l4 = lane & 3;

    const float* gQ = g_qkv[0] + ((size_t)bh*NS + qt*128)*NHD;
    const float* gK = g_qkv[1] + (size_t)bh*NS*NHD;
    const float* gV = g_qkv[2] + (size_t)bh*NS*NHD;

    load_rows<128>(sm, LDK, gQ, tid);
    __syncthreads();
    uint32_t qa[8][4];
    {
        const float* qbase = sm + (warp*16 + g4)*LDK;
#pragma unroll
        for (int kk = 0; kk < 8; kk++) {
            const float* qp = qbase + kk*8 + l4;
            qa[kk][0] = fbits(qp[0]);
            qa[kk][1] = fbits(qp[8*LDK]);
            qa[kk][2] = fbits(qp[4]);
            qa[kk][3] = fbits(qp[8*LDK + 4]);
        }
    }
    __syncthreads();

    const uint32_t sK0u = (uint32_t)__cvta_generic_to_shared(sK0);
    const uint32_t sK1u = (uint32_t)__cvta_generic_to_shared(sK1);
    const uint32_t sV0u = (uint32_t)__cvta_generic_to_shared(sV0);
    const uint32_t sV1u = (uint32_t)__cvta_generic_to_shared(sV1);

    cpa_rows<64>(sK0u, LDK, gK, 64, tid);
    cpa_rows<64>(sV0u, LDV, gV, 64, tid);
    CP_COMMIT();

    float o[8][4];
    ZERO84(o);
    float m0 = -1e30f, m1 = -1e30f, l0 = 0.f, l1 = 0.f;

    for (int jt = 0; jt < NS/64; jt++) {
        CP_WAIT0();
        __syncthreads();
        const float* sK = (jt & 1) ? sK1 : sK0;
        const float* sV = (jt & 1) ? sV1 : sV0;
        if (jt + 1 < NS/64) {
            cpa_rows<64>((jt & 1) ? sK0u : sK1u, LDK, gK + (jt+1)*64*NHD, 64, tid);
            cpa_rows<64>((jt & 1) ? sV0u : sV1u, LDV, gV + (jt+1)*64*NHD, 64, tid);
            CP_COMMIT();
        }

        float sf[8][4];
        ZERO84(sf);
        gemm_regA(sf, qa, sK, g4, l4);

        float mx0 = sf[0][0], mx1 = sf[0][2];
#pragma unroll
        for (int ns = 0; ns < 8; ns++) {
            mx0 = fmaxf(mx0, fmaxf(sf[ns][0], sf[ns][1]));
            mx1 = fmaxf(mx1, fmaxf(sf[ns][2], sf[ns][3]));
        }
        mx0 = fmaxf(mx0, __shfl_xor_sync(0xffffffffu, mx0, 1));
        mx0 = fmaxf(mx0, __shfl_xor_sync(0xffffffffu, mx0, 2));
        mx1 = fmaxf(mx1, __shfl_xor_sync(0xffffffffu, mx1, 1));
        mx1 = fmaxf(mx1, __shfl_xor_sync(0xffffffffu, mx1, 2));
        float mn0 = fmaxf(m0, mx0), mn1 = fmaxf(m1, mx1);
        float c0 = __expf(m0 - mn0), c1 = __expf(m1 - mn1);
        float s0 = 0.f, s1 = 0.f;
#pragma unroll
        for (int ns = 0; ns < 8; ns++) {
            float e0 = to_tf32(__expf(sf[ns][0] - mn0));
            float e1 = to_tf32(__expf(sf[ns][1] - mn0));
            float e2 = to_tf32(__expf(sf[ns][2] - mn1));
            float e3 = to_tf32(__expf(sf[ns][3] - mn1));
            sf[ns][0] = e0; sf[ns][1] = e1; sf[ns][2] = e2; sf[ns][3] = e3;
            s0 += e0 + e1; s1 += e2 + e3;
        }
        s0 += __shfl_xor_sync(0xffffffffu, s0, 1);
        s0 += __shfl_xor_sync(0xffffffffu, s0, 2);
        s1 += __shfl_xor_sync(0xffffffffu, s1, 1);
        s1 += __shfl_xor_sync(0xffffffffu, s1, 2);
        l0 = l0 * c0 + s0; l1 = l1 * c1 + s1;
        m0 = mn0; m1 = mn1;

#pragma unroll
        for (int ds = 0; ds < 8; ds++) {
            o[ds][0] *= c0; o[ds][1] *= c0;
            o[ds][2] *= c1; o[ds][3] *= c1;
        }

        const int srcA = (lane & ~3) + (l4 >> 1);
        const int srcB = srcA + 2;
        const bool odd = (l4 & 1);
#pragma unroll
        for (int kk = 0; kk < 8; kk++) {
            float p0 = __shfl_sync(0xffffffffu, sf[kk][0], srcA);
            float p1 = __shfl_sync(0xffffffffu, sf[kk][1], srcA);
            float p2 = __shfl_sync(0xffffffffu, sf[kk][2], srcA);
            float p3 = __shfl_sync(0xffffffffu, sf[kk][3], srcA);
            float r0 = __shfl_sync(0xffffffffu, sf[kk][0], srcB);
            float r1 = __shfl_sync(0xffffffffu, sf[kk][1], srcB);
            float r2 = __shfl_sync(0xffffffffu, sf[kk][2], srcB);
            float r3 = __shfl_sync(0xffffffffu, sf[kk][3], srcB);
            uint32_t a[4];
            a[0] = fbits(odd ? p1 : p0);
            a[1] = fbits(odd ? p3 : p2);
            a[2] = fbits(odd ? r1 : r0);
            a[3] = fbits(odd ? r3 : r2);
#pragma unroll
            for (int ds = 0; ds < 8; ds++) {
                const float* vp = sV + (kk*8 + l4)*LDV + ds*8 + g4;
                uint32_t b[2] = { fbits(vp[0]), fbits(vp[4*LDV]) };
                mma_tf32(o[ds], a, b, o[ds]);
            }
        }
    }

    const float inv0 = 1.f / l0;
    const float inv1 = 1.f / l1;
    const int b = bh >> 3, h = bh & 7;
    const int row0 = qt*128 + warp*16 + g4;
    float* base0 = g_ao + ((size_t)b*NS + row0)*ND + h*64;
    float* base1 = base0 + (size_t)8*ND;
#pragma unroll
    for (int ds = 0; ds < 8; ds++) {
        int c = ds*8 + 2*l4;
        *reinterpret_cast<float2*>(base0 + c) = make_float2(o[ds][0]*inv0, o[ds][1]*inv0);
        *reinterpret_cast<float2*>(base1 + c) = make_float2(o[ds][2]*inv1, o[ds][3]*inv1);
    }
}

// ---------------------------------------------------------------------------
// Kernel 4: final projection, FA2-style. 128x64 per block, cp.async pipeline.
// ---------------------------------------------------------------------------
#define PROJ_SMEM_FLOATS (2*128*LDK + 2*64*LDK)

__global__ void __launch_bounds__(256) k_proj(const float* __restrict__ bias,
                                              float* __restrict__ out) {
    extern __shared__ float sm[];
    float* sX0 = sm;
    float* sX1 = sm + 128*LDK;
    float* sB0 = sm + 2*128*LDK;
    float* sB1 = sB0 + 64*LDK;

    const int rt = blockIdx.x;     // 0..31
    const int ct = blockIdx.y;     // 0..7
    const int tid  = threadIdx.x;
    const int lane = tid & 31;
    const int warp = tid >> 5;
    const int g4 = lane >> 2;
    const int l4 = lane & 3;
    const int r0 = rt * 128;

    const uint32_t sX0u = (uint32_t)__cvta_generic_to_shared(sX0);
    const uint32_t sX1u = (uint32_t)__cvta_generic_to_shared(sX1);
    const uint32_t sB0u = (uint32_t)__cvta_generic_to_shared(sB0);
    const uint32_t sB1u = (uint32_t)__cvta_generic_to_shared(sB1);

    cpa_rows<128>(sX0u, LDK, g_ao + (size_t)r0*ND, ND, tid);
    cpa_rows<64> (sB0u, LDK, g_woT + (size_t)(ct*64)*512, 512, tid);
    CP_COMMIT();

    float oC[8][4];
    ZERO84(oC);
    for (int kt = 0; kt < 8; kt++) {
        CP_WAIT0();
        __syncthreads();
        if (kt + 1 < 8) {
            cpa_rows<128>((kt & 1) ? sX0u : sX1u, LDK, g_ao + (size_t)r0*ND + (kt+1)*64, ND, tid);
            cpa_rows<64> ((kt & 1) ? sB0u : sB1u, LDK, g_woT + (size_t)(ct*64)*512 + (kt+1)*64, 512, tid);
            CP_COMMIT();
        }
        const float* sX = (kt & 1) ? sX1 : sX0;
        const float* sB = (kt & 1) ? sB1 : sB0;
        const float* abase = sX + (warp*16 + g4)*LDK + l4;
#pragma unroll
        for (int kk = 0; kk < 8; kk++) {
            const float* ap = abase + kk*8;
            uint32_t a[4];
            a[0] = fbits(to_tf32(ap[0]));
            a[1] = fbits(to_tf32(ap[8*LDK]));
            a[2] = fbits(to_tf32(ap[4]));
            a[3] = fbits(to_tf32(ap[8*LDK + 4]));
#pragma unroll
            for (int ns = 0; ns < 8; ns++) {
                const float* bp = sB + (ns*8 + g4)*LDK + kk*8 + l4;
                uint32_t b[2] = { fbits(bp[0]), fbits(bp[4]) };
                mma_tf32(oC[ns], a, b, oC[ns]);
            }
        }
    }

    const int gr_ = r0 + warp*16 + g4;
#pragma unroll
    for (int ns = 0; ns < 8; ns++) {
        int c = ct*64 + ns*8 + 2*l4;
        out[(size_t)gr_*ND + c]       = oC[ns][0] + bias[c];
        out[(size_t)gr_*ND + c + 1]   = oC[ns][1] + bias[c + 1];
        out[(size_t)(gr_+8)*ND + c]   = oC[ns][2] + bias[c];
        out[(size_t)(gr_+8)*ND + c+1] = oC[ns][3] + bias[c + 1];
    }
}

// ---------------------------------------------------------------------------
extern "C" void kernel_launch(void* const* d_in, const int* in_sizes, int n_in,
                              void* d_out, int out_size) {
    const float* x      = (const float*)d_in[0];
    const float* q_enc  = (const float*)d_in[1];
    const float* q_gr   = (const float*)d_in[2];
    const float* q_gi   = (const float*)d_in[3];
    const float* q_ent  = (const float*)d_in[4];
    const float* q_meas = (const float*)d_in[5];
    const float* k_enc  = (const float*)d_in[6];
    const float* k_gr   = (const float*)d_in[7];
    const float* k_gi   = (const float*)d_in[8];
    const float* k_ent  = (const float*)d_in[9];
    const float* k_meas = (const float*)d_in[10];
    const float* v_enc  = (const float*)d_in[11];
    const float* v_gr   = (const float*)d_in[12];
    const float* v_gi   = (const float*)d_in[13];
    const float* v_ent  = (const float*)d_in[14];
    const float* v_meas = (const float*)d_in[15];
    const float* sup_w  = (const float*)d_in[16];
    const float* interf = (const float*)d_in[17];
    const float* w_out  = (const float*)d_in[18];
    const float* b_out  = (const float*)d_in[19];
    float* out = (float*)d_out;

    static const int ATT_SMEM  = ATT_SMEM_FLOATS  * (int)sizeof(float);  // 71680 B
    static const int QNL_SMEM  = QNL_SMEM_FLOATS  * (int)sizeof(float);  // 104448 B
    static const int PROJ_SMEM = PROJ_SMEM_FLOATS * (int)sizeof(float);  // 104448 B
    cudaFuncSetAttribute(k_attn, cudaFuncAttributeMaxDynamicSharedMemorySize, ATT_SMEM);
    cudaFuncSetAttribute(k_qnl,  cudaFuncAttributeMaxDynamicSharedMemorySize, QNL_SMEM);
    cudaFuncSetAttribute(k_proj, cudaFuncAttributeMaxDynamicSharedMemorySize, PROJ_SMEM);

    k_prep<<<83, 256>>>(q_gr, q_gi, q_ent, k_gr, k_gi, k_ent, v_gr, v_gi, v_ent,
                        q_meas, k_meas, v_meas, q_enc, k_enc, v_enc,
                        sup_w, interf, w_out);
    k_qnl<<<3 * (NBS/128), 256, QNL_SMEM>>>(x);
    k_attn<<<NB*NH*(NS/128), 256, ATT_SMEM>>>();
    k_proj<<<dim3(NBS/128, ND/64), 256, PROJ_SMEM>>>(b_out, out);
}